// round 5
// baseline (speedup 1.0000x reference)
#include <cuda_runtime.h>
#include <cuda_bf16.h>
#include <math.h>
#include <stdint.h>

#define B_  2
#define S_  2048
#define D_  1024
#define H_  16
#define DK_ 64
#define M_  (B_*S_)   // 4096

// ---- scratch (static device globals; no allocation allowed) ----
__device__ float g_S[(size_t)B_*H_*S_*S_];                 // fp32 scores (512MB)
__device__ __nv_bfloat16 g_Ph[(size_t)B_*H_*S_*S_];        // probs hi (256MB)
__device__ __nv_bfloat16 g_Pl[(size_t)B_*H_*S_*S_];        // probs lo (256MB)
__device__ __nv_bfloat16 g_Qh[(size_t)M_*D_], g_Ql[(size_t)M_*D_];
__device__ __nv_bfloat16 g_Kh[(size_t)M_*D_], g_Kl[(size_t)M_*D_];
__device__ __nv_bfloat16 g_Vh[(size_t)M_*D_], g_Vl[(size_t)M_*D_];
__device__ __nv_bfloat16 g_HOh[(size_t)M_*D_], g_HOl[(size_t)M_*D_];
__device__ __nv_bfloat16 g_xqh[(size_t)M_*D_], g_xql[(size_t)M_*D_];
__device__ __nv_bfloat16 g_xkh[(size_t)M_*D_], g_xkl[(size_t)M_*D_];
__device__ __nv_bfloat16 g_xvh[(size_t)M_*D_], g_xvl[(size_t)M_*D_];
__device__ __nv_bfloat16 g_wqh[(size_t)D_*D_], g_wql[(size_t)D_*D_];
__device__ __nv_bfloat16 g_wkh[(size_t)D_*D_], g_wkl[(size_t)D_*D_];
__device__ __nv_bfloat16 g_wvh[(size_t)D_*D_], g_wvl[(size_t)D_*D_];
__device__ __nv_bfloat16 g_woh[(size_t)D_*D_], g_wol[(size_t)D_*D_];

// ============================================================
// helpers
// ============================================================
__device__ __forceinline__ uint32_t smem_u32(const void* p) {
    return (uint32_t)__cvta_generic_to_shared(p);
}
__device__ __forceinline__ void cpasync16(void* s, const void* g) {
    asm volatile("cp.async.cg.shared.global [%0], [%1], 16;\n"
                 :: "r"(smem_u32(s)), "l"(g));
}
#define CP_COMMIT() asm volatile("cp.async.commit_group;\n" ::)
#define CP_WAIT1()  asm volatile("cp.async.wait_group 1;\n" ::)

__device__ __forceinline__ void ldsm_x4(uint32_t* r, uint32_t a) {
    asm volatile("ldmatrix.sync.aligned.m8n8.x4.shared.b16 {%0,%1,%2,%3}, [%4];"
                 : "=r"(r[0]), "=r"(r[1]), "=r"(r[2]), "=r"(r[3]) : "r"(a));
}
__device__ __forceinline__ void ldsm_x4_t(uint32_t* r, uint32_t a) {
    asm volatile("ldmatrix.sync.aligned.m8n8.x4.trans.shared.b16 {%0,%1,%2,%3}, [%4];"
                 : "=r"(r[0]), "=r"(r[1]), "=r"(r[2]), "=r"(r[3]) : "r"(a));
}
__device__ __forceinline__ void mma16816(float* c, const uint32_t* a,
                                         uint32_t b0, uint32_t b1) {
    asm volatile(
        "mma.sync.aligned.m16n8k16.row.col.f32.bf16.bf16.f32 "
        "{%0,%1,%2,%3},{%4,%5,%6,%7},{%8,%9},{%0,%1,%2,%3};"
        : "+f"(c[0]), "+f"(c[1]), "+f"(c[2]), "+f"(c[3])
        : "r"(a[0]), "r"(a[1]), "r"(a[2]), "r"(a[3]), "r"(b0), "r"(b1));
}

// split fp32 -> bf16 hi + lo
__device__ __forceinline__ void split1(float v, __nv_bfloat16& h, __nv_bfloat16& l) {
    h = __float2bfloat16_rn(v);
    l = __float2bfloat16_rn(v - __bfloat162float(h));
}

// ============================================================
// elementwise fp32 -> (hi, lo) bf16 converter
// ============================================================
__global__ __launch_bounds__(256) void split_convert(
    const float* __restrict__ x, __nv_bfloat16* __restrict__ xh,
    __nv_bfloat16* __restrict__ xl, int n4)
{
    int i = blockIdx.x * blockDim.x + threadIdx.x;
    if (i >= n4) return;
    float4 v = *(const float4*)(x + (size_t)i * 4);
    __nv_bfloat16 h0,h1,h2,h3,l0,l1,l2,l3;
    split1(v.x,h0,l0); split1(v.y,h1,l1); split1(v.z,h2,l2); split1(v.w,h3,l3);
    *(__nv_bfloat162*)(xh + (size_t)i*4)     = __halves2bfloat162(h0,h1);
    *(__nv_bfloat162*)(xh + (size_t)i*4 + 2) = __halves2bfloat162(h2,h3);
    *(__nv_bfloat162*)(xl + (size_t)i*4)     = __halves2bfloat162(l0,l1);
    *(__nv_bfloat162*)(xl + (size_t)i*4 + 2) = __halves2bfloat162(l2,l3);
}

// ============================================================
// Batched NT GEMM, bf16 hi/lo operands, cp.async 2-stage pipeline.
//   C[m,n] = alpha * sum_k (Ah+Al)[m,k] * (Bh+Bl)[n,k]   (3-term)
// Block 128x128, BK=16, 256 threads, 8 warps 2x4, warp tile 64x32.
// MODE 0: fp32 C0.  MODE 1: split write Ch/Cl.
// ============================================================
#define PAD 24
template<int MODE>
__global__ __launch_bounds__(256, 1) void gemm_hl_nt(
    const __nv_bfloat16* __restrict__ Ah, const __nv_bfloat16* __restrict__ Al,
    int lda, long sAb, long sAh_,
    const __nv_bfloat16* __restrict__ Bh, const __nv_bfloat16* __restrict__ Bl,
    int ldb, long sBb, long sBh_,
    float* __restrict__ C0, __nv_bfloat16* __restrict__ Ch,
    __nv_bfloat16* __restrict__ Cl, int ldc, long sCb, long sCh_,
    int K, float alpha, int HB)
{
    const int z  = blockIdx.z;
    const int zb = z / HB, zh = z % HB;
    Ah += (size_t)zb * sAb + (size_t)zh * sAh_;
    Al += (size_t)zb * sAb + (size_t)zh * sAh_;
    Bh += (size_t)zb * sBb + (size_t)zh * sBh_;
    Bl += (size_t)zb * sBb + (size_t)zh * sBh_;
    const size_t coff = (size_t)zb * sCb + (size_t)zh * sCh_;

    __shared__ __nv_bfloat16 sA[2][2][128][PAD];
    __shared__ __nv_bfloat16 sB[2][2][128][PAD];

    const int tid  = threadIdx.x;
    const int lane = tid & 31;
    const int warp = tid >> 5;
    const int wm   = (warp >> 2) * 64;
    const int wn   = (warp & 3) * 32;
    const int bm   = blockIdx.y * 128;
    const int bn   = blockIdx.x * 128;

    const int lrow = tid >> 1;          // 0..127
    const int lch  = (tid & 1) * 8;     // elem offset 0/8

    float acc[4][4][4];
    #pragma unroll
    for (int i = 0; i < 4; i++)
        #pragma unroll
        for (int j = 0; j < 4; j++)
            #pragma unroll
            for (int c = 0; c < 4; c++) acc[i][j][c] = 0.f;

    const int lrow16 = lane & 15;
    const int ksub   = (lane >> 4) * 8;
    const int KT = K >> 4;

    // prologue
    {
        const size_t ar = (size_t)(bm + lrow) * lda + lch;
        const size_t br = (size_t)(bn + lrow) * ldb + lch;
        cpasync16(&sA[0][0][lrow][lch], Ah + ar);
        cpasync16(&sA[0][1][lrow][lch], Al + ar);
        cpasync16(&sB[0][0][lrow][lch], Bh + br);
        cpasync16(&sB[0][1][lrow][lch], Bl + br);
    }
    CP_COMMIT();

    for (int kt = 0; kt < KT; kt++) {
        const int st = kt & 1;
        if (kt + 1 < KT) {
            const int k0 = (kt + 1) << 4;
            const size_t ar = (size_t)(bm + lrow) * lda + k0 + lch;
            const size_t br = (size_t)(bn + lrow) * ldb + k0 + lch;
            cpasync16(&sA[st^1][0][lrow][lch], Ah + ar);
            cpasync16(&sA[st^1][1][lrow][lch], Al + ar);
            cpasync16(&sB[st^1][0][lrow][lch], Bh + br);
            cpasync16(&sB[st^1][1][lrow][lch], Bl + br);
        }
        CP_COMMIT();
        CP_WAIT1();
        __syncthreads();

        uint32_t ah[4][4], al[4][4], bh[4][2], bl[4][2];
        #pragma unroll
        for (int mi = 0; mi < 4; mi++) {
            ldsm_x4(ah[mi], smem_u32(&sA[st][0][wm + mi*16 + lrow16][ksub]));
            ldsm_x4(al[mi], smem_u32(&sA[st][1][wm + mi*16 + lrow16][ksub]));
        }
        #pragma unroll
        for (int np = 0; np < 2; np++) {
            uint32_t r[4];
            ldsm_x4(r, smem_u32(&sB[st][0][wn + np*16 + lrow16][ksub]));
            bh[2*np][0] = r[0]; bh[2*np+1][0] = r[1];
            bh[2*np][1] = r[2]; bh[2*np+1][1] = r[3];
            ldsm_x4(r, smem_u32(&sB[st][1][wn + np*16 + lrow16][ksub]));
            bl[2*np][0] = r[0]; bl[2*np+1][0] = r[1];
            bl[2*np][1] = r[2]; bl[2*np+1][1] = r[3];
        }

        #pragma unroll
        for (int mi = 0; mi < 4; mi++)
            #pragma unroll
            for (int ni = 0; ni < 4; ni++) {
                mma16816(acc[mi][ni], ah[mi], bh[ni][0], bh[ni][1]);
                mma16816(acc[mi][ni], ah[mi], bl[ni][0], bl[ni][1]);
                mma16816(acc[mi][ni], al[mi], bh[ni][0], bh[ni][1]);
            }
        __syncthreads();
    }

    const int g = lane >> 2, tg = lane & 3;
    #pragma unroll
    for (int mi = 0; mi < 4; mi++) {
        const int r0 = bm + wm + mi * 16 + g;
        #pragma unroll
        for (int ni = 0; ni < 4; ni++) {
            const int c0 = bn + wn + ni * 8 + tg * 2;
            float v00 = alpha * acc[mi][ni][0], v01 = alpha * acc[mi][ni][1];
            float v10 = alpha * acc[mi][ni][2], v11 = alpha * acc[mi][ni][3];
            if (MODE == 0) {
                *(float2*)&C0[coff + (size_t)r0 * ldc + c0]       = make_float2(v00, v01);
                *(float2*)&C0[coff + (size_t)(r0 + 8) * ldc + c0] = make_float2(v10, v11);
            } else {
                __nv_bfloat16 h0,h1,l0,l1;
                split1(v00,h0,l0); split1(v01,h1,l1);
                *(__nv_bfloat162*)&Ch[coff + (size_t)r0 * ldc + c0] = __halves2bfloat162(h0,h1);
                *(__nv_bfloat162*)&Cl[coff + (size_t)r0 * ldc + c0] = __halves2bfloat162(l0,l1);
                split1(v10,h0,l0); split1(v11,h1,l1);
                *(__nv_bfloat162*)&Ch[coff + (size_t)(r0+8) * ldc + c0] = __halves2bfloat162(h0,h1);
                *(__nv_bfloat162*)&Cl[coff + (size_t)(r0+8) * ldc + c0] = __halves2bfloat162(l0,l1);
            }
        }
    }
}

// ============================================================
// Fused softmax + head-mean. Reads fp32 scores, writes bf16 hi/lo probs
// + fp32 attn_weights.
// ============================================================
__global__ __launch_bounds__(256) void softmax_mean(
    const float* __restrict__ Sc, __nv_bfloat16* __restrict__ Ph,
    __nv_bfloat16* __restrict__ Pl, float* __restrict__ W)
{
    const int b = blockIdx.x >> 11;
    const int s = blockIdx.x & (S_ - 1);
    const int tid = threadIdx.x;
    const int lane = tid & 31, wid = tid >> 5;

    __shared__ float red[8];

    float acc[8];
    #pragma unroll
    for (int i = 0; i < 8; i++) acc[i] = 0.f;

    const int c0 = tid * 4;
    const int c1 = 1024 + tid * 4;

    for (int h = 0; h < H_; h++) {
        const size_t ro = ((size_t)(b * H_ + h) * S_ + s) * S_;
        float v[8];
        float4 f0 = *(const float4*)(Sc + ro + c0);
        float4 f1 = *(const float4*)(Sc + ro + c1);
        v[0]=f0.x; v[1]=f0.y; v[2]=f0.z; v[3]=f0.w;
        v[4]=f1.x; v[5]=f1.y; v[6]=f1.z; v[7]=f1.w;

        float m = v[0];
        #pragma unroll
        for (int i = 1; i < 8; i++) m = fmaxf(m, v[i]);
        #pragma unroll
        for (int o = 16; o > 0; o >>= 1) m = fmaxf(m, __shfl_xor_sync(0xffffffff, m, o));
        if (lane == 0) red[wid] = m;
        __syncthreads();
        if (wid == 0) {
            float t = red[lane & 7];
            #pragma unroll
            for (int o = 4; o > 0; o >>= 1) t = fmaxf(t, __shfl_xor_sync(0xffffffff, t, o));
            if (lane == 0) red[0] = t;
        }
        __syncthreads();
        m = red[0];
        __syncthreads();

        float sloc = 0.f;
        #pragma unroll
        for (int i = 0; i < 8; i++) { v[i] = __expf(v[i] - m); sloc += v[i]; }
        #pragma unroll
        for (int o = 16; o > 0; o >>= 1) sloc += __shfl_xor_sync(0xffffffff, sloc, o);
        if (lane == 0) red[wid] = sloc;
        __syncthreads();
        if (wid == 0) {
            float t = red[lane & 7];
            #pragma unroll
            for (int o = 4; o > 0; o >>= 1) t += __shfl_xor_sync(0xffffffff, t, o);
            if (lane == 0) red[0] = t;
        }
        __syncthreads();
        float inv = 1.0f / red[0];
        __syncthreads();

        __nv_bfloat16 ph[8], pl[8];
        #pragma unroll
        for (int i = 0; i < 8; i++) {
            v[i] *= inv;
            acc[i] += v[i] * (1.0f / H_);
            split1(v[i], ph[i], pl[i]);
        }
        *(__nv_bfloat162*)(Ph + ro + c0)     = __halves2bfloat162(ph[0], ph[1]);
        *(__nv_bfloat162*)(Ph + ro + c0 + 2) = __halves2bfloat162(ph[2], ph[3]);
        *(__nv_bfloat162*)(Ph + ro + c1)     = __halves2bfloat162(ph[4], ph[5]);
        *(__nv_bfloat162*)(Ph + ro + c1 + 2) = __halves2bfloat162(ph[6], ph[7]);
        *(__nv_bfloat162*)(Pl + ro + c0)     = __halves2bfloat162(pl[0], pl[1]);
        *(__nv_bfloat162*)(Pl + ro + c0 + 2) = __halves2bfloat162(pl[2], pl[3]);
        *(__nv_bfloat162*)(Pl + ro + c1)     = __halves2bfloat162(pl[4], pl[5]);
        *(__nv_bfloat162*)(Pl + ro + c1 + 2) = __halves2bfloat162(pl[6], pl[7]);
    }

    float* wrow = W + ((size_t)b * S_ + s) * S_;
    *(float4*)(wrow + c0) = make_float4(acc[0], acc[1], acc[2], acc[3]);
    *(float4*)(wrow + c1) = make_float4(acc[4], acc[5], acc[6], acc[7]);
}

// ============================================================
// attn @ V: O[s,d] = sum_k P[s,k]*V[k,d] per (b,h); bf16 hi/lo operands,
// cp.async 2-stage. Block 128x64, BK=16, 8 warps 4x2, warp 32x32.
// Writes split HO (hi/lo).
// ============================================================
#define VPAD 72
__global__ __launch_bounds__(256, 1) void av_hl(
    const __nv_bfloat16* __restrict__ Ph, const __nv_bfloat16* __restrict__ Pl,
    const __nv_bfloat16* __restrict__ Vh, const __nv_bfloat16* __restrict__ Vl,
    __nv_bfloat16* __restrict__ Oh, __nv_bfloat16* __restrict__ Ol)
{
    const int z = blockIdx.z;
    const int b = z / H_, h = z % H_;
    const size_t po = (size_t)z * S_ * S_;
    const size_t vo = (size_t)b * S_ * D_ + h * DK_;

    __shared__ __nv_bfloat16 sP[2][2][128][PAD];
    __shared__ __nv_bfloat16 sV[2][2][16][VPAD];

    const int tid  = threadIdx.x;
    const int lane = tid & 31;
    const int warp = tid >> 5;
    const int wm   = (warp >> 1) * 32;
    const int wn   = (warp & 1) * 32;
    const int bm   = blockIdx.x * 128;

    const int lrow = tid >> 1;           // 0..127 (P rows)
    const int lch  = (tid & 1) * 8;
    const int vrow = tid >> 3;           // 0..31 (use <16)
    const int vch  = (tid & 7) * 8;

    float acc[2][4][4];
    #pragma unroll
    for (int i = 0; i < 2; i++)
        #pragma unroll
        for (int j = 0; j < 4; j++)
            #pragma unroll
            for (int c = 0; c < 4; c++) acc[i][j][c] = 0.f;

    const int lrow16 = lane & 15;
    const int ksub   = (lane >> 4) * 8;
    const int KT = S_ >> 4;   // 128

    // prologue
    {
        const size_t pr = po + (size_t)(bm + lrow) * S_ + lch;
        cpasync16(&sP[0][0][lrow][lch], Ph + pr);
        cpasync16(&sP[0][1][lrow][lch], Pl + pr);
        if (vrow < 16) {
            const size_t vr = vo + (size_t)vrow * D_ + vch;
            cpasync16(&sV[0][0][vrow][vch], Vh + vr);
            cpasync16(&sV[0][1][vrow][vch], Vl + vr);
        }
    }
    CP_COMMIT();

    for (int kt = 0; kt < KT; kt++) {
        const int st = kt & 1;
        if (kt + 1 < KT) {
            const int k0 = (kt + 1) << 4;
            const size_t pr = po + (size_t)(bm + lrow) * S_ + k0 + lch;
            cpasync16(&sP[st^1][0][lrow][lch], Ph + pr);
            cpasync16(&sP[st^1][1][lrow][lch], Pl + pr);
            if (vrow < 16) {
                const size_t vr = vo + (size_t)(k0 + vrow) * D_ + vch;
                cpasync16(&sV[st^1][0][vrow][vch], Vh + vr);
                cpasync16(&sV[st^1][1][vrow][vch], Vl + vr);
            }
        }
        CP_COMMIT();
        CP_WAIT1();
        __syncthreads();

        uint32_t ah[2][4], al[2][4], bh[4][2], bl[4][2];
        #pragma unroll
        for (int mi = 0; mi < 2; mi++) {
            ldsm_x4(ah[mi], smem_u32(&sP[st][0][wm + mi*16 + lrow16][ksub]));
            ldsm_x4(al[mi], smem_u32(&sP[st][1][wm + mi*16 + lrow16][ksub]));
        }
        #pragma unroll
        for (int np = 0; np < 2; np++) {
            uint32_t r[4];
            ldsm_x4_t(r, smem_u32(&sV[st][0][lrow16][wn + np*16 + ksub]));
            bh[2*np][0] = r[0]; bh[2*np][1] = r[1];
            bh[2*np+1][0] = r[2]; bh[2*np+1][1] = r[3];
            ldsm_x4_t(r, smem_u32(&sV[st][1][lrow16][wn + np*16 + ksub]));
            bl[2*np][0] = r[0]; bl[2*np][1] = r[1];
            bl[2*np+1][0] = r[2]; bl[2*np+1][1] = r[3];
        }

        #pragma unroll
        for (int mi = 0; mi < 2; mi++)
            #pragma unroll
            for (int ni = 0; ni < 4; ni++) {
                mma16816(acc[mi][ni], ah[mi], bh[ni][0], bh[ni][1]);
                mma16816(acc[mi][ni], ah[mi], bl[ni][0], bl[ni][1]);
                mma16816(acc[mi][ni], al[mi], bh[ni][0], bh[ni][1]);
            }
        __syncthreads();
    }

    const int g = lane >> 2, tg = lane & 3;
    #pragma unroll
    for (int mi = 0; mi < 2; mi++) {
        const int r0 = bm + wm + mi * 16 + g;
        #pragma unroll
        for (int ni = 0; ni < 4; ni++) {
            const int c0 = wn + ni * 8 + tg * 2;
            __nv_bfloat16 h0,h1,l0,l1;
            split1(acc[mi][ni][0], h0, l0); split1(acc[mi][ni][1], h1, l1);
            *(__nv_bfloat162*)&Oh[vo + (size_t)r0 * D_ + c0] = __halves2bfloat162(h0,h1);
            *(__nv_bfloat162*)&Ol[vo + (size_t)r0 * D_ + c0] = __halves2bfloat162(l0,l1);
            split1(acc[mi][ni][2], h0, l0); split1(acc[mi][ni][3], h1, l1);
            *(__nv_bfloat162*)&Oh[vo + (size_t)(r0+8) * D_ + c0] = __halves2bfloat162(h0,h1);
            *(__nv_bfloat162*)&Ol[vo + (size_t)(r0+8) * D_ + c0] = __halves2bfloat162(l0,l1);
        }
    }
}

// ============================================================
extern "C" void kernel_launch(void* const* d_in, const int* in_sizes, int n_in,
                              void* d_out, int out_size)
{
    const float* query = (const float*)d_in[0];
    const float* key   = (const float*)d_in[1];
    const float* value = (const float*)d_in[2];
    const float* W_q   = (const float*)d_in[3];
    const float* W_k   = (const float*)d_in[4];
    const float* W_v   = (const float*)d_in[5];
    const float* W_o   = (const float*)d_in[6];

    float* out   = (float*)d_out;
    float* attnw = out + (size_t)M_ * D_;

    float *Sc;
    __nv_bfloat16 *Ph, *Pl, *Qh, *Ql, *Kh, *Kl, *Vh, *Vl, *HOh, *HOl;
    __nv_bfloat16 *xqh, *xql, *xkh, *xkl, *xvh, *xvl;
    __nv_bfloat16 *wqh, *wql, *wkh, *wkl, *wvh, *wvl, *woh, *wol;
    cudaGetSymbolAddress((void**)&Sc,  g_S);
    cudaGetSymbolAddress((void**)&Ph,  g_Ph);
    cudaGetSymbolAddress((void**)&Pl,  g_Pl);
    cudaGetSymbolAddress((void**)&Qh,  g_Qh);  cudaGetSymbolAddress((void**)&Ql, g_Ql);
    cudaGetSymbolAddress((void**)&Kh,  g_Kh);  cudaGetSymbolAddress((void**)&Kl, g_Kl);
    cudaGetSymbolAddress((void**)&Vh,  g_Vh);  cudaGetSymbolAddress((void**)&Vl, g_Vl);
    cudaGetSymbolAddress((void**)&HOh, g_HOh); cudaGetSymbolAddress((void**)&HOl, g_HOl);
    cudaGetSymbolAddress((void**)&xqh, g_xqh); cudaGetSymbolAddress((void**)&xql, g_xql);
    cudaGetSymbolAddress((void**)&xkh, g_xkh); cudaGetSymbolAddress((void**)&xkl, g_xkl);
    cudaGetSymbolAddress((void**)&xvh, g_xvh); cudaGetSymbolAddress((void**)&xvl, g_xvl);
    cudaGetSymbolAddress((void**)&wqh, g_wqh); cudaGetSymbolAddress((void**)&wql, g_wql);
    cudaGetSymbolAddress((void**)&wkh, g_wkh); cudaGetSymbolAddress((void**)&wkl, g_wkl);
    cudaGetSymbolAddress((void**)&wvh, g_wvh); cudaGetSymbolAddress((void**)&wvl, g_wvl);
    cudaGetSymbolAddress((void**)&woh, g_woh); cudaGetSymbolAddress((void**)&wol, g_wol);

    dim3 blk(256);

    // 0) split-convert raw inputs
    {
        const int nx4 = (M_ * D_) / 4, nw4 = (D_ * D_) / 4;
        split_convert<<<(nx4 + 255) / 256, blk>>>(query, xqh, xql, nx4);
        split_convert<<<(nx4 + 255) / 256, blk>>>(key,   xkh, xkl, nx4);
        split_convert<<<(nx4 + 255) / 256, blk>>>(value, xvh, xvl, nx4);
        split_convert<<<(nw4 + 255) / 256, blk>>>(W_q, wqh, wql, nw4);
        split_convert<<<(nw4 + 255) / 256, blk>>>(W_k, wkh, wkl, nw4);
        split_convert<<<(nw4 + 255) / 256, blk>>>(W_v, wvh, wvl, nw4);
        split_convert<<<(nw4 + 255) / 256, blk>>>(W_o, woh, wol, nw4);
    }

    // 1) Projections (split outputs)
    {
        dim3 grid(D_/128, M_/128, 1);
        gemm_hl_nt<1><<<grid, blk>>>(xqh, xql, D_, 0, 0, wqh, wql, D_, 0, 0,
                                     nullptr, Qh, Ql, D_, 0, 0, D_, 1.0f, 1);
        gemm_hl_nt<1><<<grid, blk>>>(xkh, xkl, D_, 0, 0, wkh, wkl, D_, 0, 0,
                                     nullptr, Kh, Kl, D_, 0, 0, D_, 1.0f, 1);
        gemm_hl_nt<1><<<grid, blk>>>(xvh, xvl, D_, 0, 0, wvh, wvl, D_, 0, 0,
                                     nullptr, Vh, Vl, D_, 0, 0, D_, 1.0f, 1);
    }

    // 2) Scores (fp32 out)
    {
        dim3 grid(S_/128, S_/128, B_ * H_);
        gemm_hl_nt<0><<<grid, blk>>>(
            Qh, Ql, D_, (long)S_ * D_, DK_,
            Kh, Kl, D_, (long)S_ * D_, DK_,
            Sc, nullptr, nullptr, S_, (long)H_ * S_ * S_, (long)S_ * S_,
            DK_, 0.125f, H_);
    }

    // 3) Softmax + head mean (probs hi/lo out)
    softmax_mean<<<dim3(B_ * S_), blk>>>(Sc, Ph, Pl, attnw);

    // 4) head_out = attn @ V (split out)
    av_hl<<<dim3(S_/128, 1, B_ * H_), blk>>>(Ph, Pl, Vh, Vl, HOh, HOl);

    // 5) out = head_out @ W_o^T (fp32 out)
    {
        dim3 grid(D_/128, M_/128, 1);
        gemm_hl_nt<0><<<grid, blk>>>(HOh, HOl, D_, 0, 0, woh, wol, D_, 0, 0,
                                     out, nullptr, nullptr, D_, 0, 0, D_, 1.0f, 1);
    }
}

// round 6
// speedup vs baseline: 1.5074x; 1.5074x over previous
#include <cuda_runtime.h>
#include <cuda_bf16.h>
#include <math.h>
#include <stdint.h>

#define B_  2
#define S_  2048
#define D_  1024
#define H_  16
#define DK_ 64
#define M_  (B_*S_)   // 4096

// ---- scratch (static device globals; no allocation allowed) ----
__device__ float g_S[(size_t)B_*H_*S_*S_];                 // fp32 scores (512MB)
__device__ __nv_bfloat16 g_Ph[(size_t)B_*H_*S_*S_];        // probs hi (256MB)
__device__ __nv_bfloat16 g_Pl[(size_t)B_*H_*S_*S_];        // probs lo (256MB)
__device__ __nv_bfloat16 g_Qh[(size_t)M_*D_], g_Ql[(size_t)M_*D_];
__device__ __nv_bfloat16 g_Kh[(size_t)M_*D_], g_Kl[(size_t)M_*D_];
__device__ __nv_bfloat16 g_Vh[(size_t)M_*D_], g_Vl[(size_t)M_*D_];
__device__ __nv_bfloat16 g_HOh[(size_t)M_*D_], g_HOl[(size_t)M_*D_];
__device__ __nv_bfloat16 g_xqh[(size_t)M_*D_], g_xql[(size_t)M_*D_];
__device__ __nv_bfloat16 g_xkh[(size_t)M_*D_], g_xkl[(size_t)M_*D_];
__device__ __nv_bfloat16 g_xvh[(size_t)M_*D_], g_xvl[(size_t)M_*D_];
__device__ __nv_bfloat16 g_wqh[(size_t)D_*D_], g_wql[(size_t)D_*D_];
__device__ __nv_bfloat16 g_wkh[(size_t)D_*D_], g_wkl[(size_t)D_*D_];
__device__ __nv_bfloat16 g_wvh[(size_t)D_*D_], g_wvl[(size_t)D_*D_];
__device__ __nv_bfloat16 g_woh[(size_t)D_*D_], g_wol[(size_t)D_*D_];

// ============================================================
// helpers
// ============================================================
__device__ __forceinline__ uint32_t smem_u32(const void* p) {
    return (uint32_t)__cvta_generic_to_shared(p);
}
__device__ __forceinline__ void cpasync16(void* s, const void* g) {
    asm volatile("cp.async.cg.shared.global [%0], [%1], 16;\n"
                 :: "r"(smem_u32(s)), "l"(g));
}
#define CP_COMMIT() asm volatile("cp.async.commit_group;\n" ::)
#define CP_WAIT1()  asm volatile("cp.async.wait_group 1;\n" ::)

__device__ __forceinline__ void ldsm_x4(uint32_t* r, uint32_t a) {
    asm volatile("ldmatrix.sync.aligned.m8n8.x4.shared.b16 {%0,%1,%2,%3}, [%4];"
                 : "=r"(r[0]), "=r"(r[1]), "=r"(r[2]), "=r"(r[3]) : "r"(a));
}
__device__ __forceinline__ void ldsm_x4_t(uint32_t* r, uint32_t a) {
    asm volatile("ldmatrix.sync.aligned.m8n8.x4.trans.shared.b16 {%0,%1,%2,%3}, [%4];"
                 : "=r"(r[0]), "=r"(r[1]), "=r"(r[2]), "=r"(r[3]) : "r"(a));
}
__device__ __forceinline__ void mma16816(float* c, const uint32_t* a,
                                         uint32_t b0, uint32_t b1) {
    asm volatile(
        "mma.sync.aligned.m16n8k16.row.col.f32.bf16.bf16.f32 "
        "{%0,%1,%2,%3},{%4,%5,%6,%7},{%8,%9},{%0,%1,%2,%3};"
        : "+f"(c[0]), "+f"(c[1]), "+f"(c[2]), "+f"(c[3])
        : "r"(a[0]), "r"(a[1]), "r"(a[2]), "r"(a[3]), "r"(b0), "r"(b1));
}

// split fp32 -> bf16 hi + lo
__device__ __forceinline__ void split1(float v, __nv_bfloat16& h, __nv_bfloat16& l) {
    h = __float2bfloat16_rn(v);
    l = __float2bfloat16_rn(v - __bfloat162float(h));
}

// ============================================================
// one-shot grid-stride converter for all 7 input tensors
// ============================================================
#define NX4 ((M_*D_)/4)   // 1,048,576 float4 per x tensor
#define NW4 ((D_*D_)/4)   // 262,144 float4 per w tensor
__global__ __launch_bounds__(256) void split_convert_all(
    const float* __restrict__ xq, const float* __restrict__ xk,
    const float* __restrict__ xv, const float* __restrict__ wq,
    const float* __restrict__ wk, const float* __restrict__ wv,
    const float* __restrict__ wo,
    __nv_bfloat16* __restrict__ xqh, __nv_bfloat16* __restrict__ xql,
    __nv_bfloat16* __restrict__ xkh, __nv_bfloat16* __restrict__ xkl,
    __nv_bfloat16* __restrict__ xvh, __nv_bfloat16* __restrict__ xvl,
    __nv_bfloat16* __restrict__ wqh, __nv_bfloat16* __restrict__ wql,
    __nv_bfloat16* __restrict__ wkh, __nv_bfloat16* __restrict__ wkl,
    __nv_bfloat16* __restrict__ wvh, __nv_bfloat16* __restrict__ wvl,
    __nv_bfloat16* __restrict__ woh, __nv_bfloat16* __restrict__ wol)
{
    const int total = 3 * NX4 + 4 * NW4;
    for (int i = blockIdx.x * blockDim.x + threadIdx.x; i < total;
         i += gridDim.x * blockDim.x) {
        const float* src; __nv_bfloat16 *dh, *dl; int j = i;
        if (j < NX4)            { src = xq; dh = xqh; dl = xql; }
        else if ((j -= NX4) < NX4) { src = xk; dh = xkh; dl = xkl; }
        else if ((j -= NX4) < NX4) { src = xv; dh = xvh; dl = xvl; }
        else if ((j -= NX4) < NW4) { src = wq; dh = wqh; dl = wql; }
        else if ((j -= NW4) < NW4) { src = wk; dh = wkh; dl = wkl; }
        else if ((j -= NW4) < NW4) { src = wv; dh = wvh; dl = wvl; }
        else      { j -= NW4;    src = wo; dh = woh; dl = wol; }
        float4 v = *(const float4*)(src + (size_t)j * 4);
        __nv_bfloat16 h0,h1,h2,h3,l0,l1,l2,l3;
        split1(v.x,h0,l0); split1(v.y,h1,l1); split1(v.z,h2,l2); split1(v.w,h3,l3);
        *(__nv_bfloat162*)(dh + (size_t)j*4)     = __halves2bfloat162(h0,h1);
        *(__nv_bfloat162*)(dh + (size_t)j*4 + 2) = __halves2bfloat162(h2,h3);
        *(__nv_bfloat162*)(dl + (size_t)j*4)     = __halves2bfloat162(l0,l1);
        *(__nv_bfloat162*)(dl + (size_t)j*4 + 2) = __halves2bfloat162(l2,l3);
    }
}

// ============================================================
// Batched NT GEMM, bf16 hi/lo operands, cp.async 2-stage pipeline.
//   C[m,n] = alpha * sum_k (Ah+Al)[m,k] * (Bh+Bl)[n,k]   (3-term)
// Block 128x128, BK=16, 256 threads, 8 warps 2x4, warp tile 64x32.
// __launch_bounds__(256, 2): cap regs at 128 -> 2 CTAs/SM (16 warps).
// MODE 0: fp32 C0.  MODE 1: split write Ch/Cl.
// ============================================================
#define PAD 24
template<int MODE>
__global__ __launch_bounds__(256, 2) void gemm_hl_nt(
    const __nv_bfloat16* __restrict__ Ah, const __nv_bfloat16* __restrict__ Al,
    int lda, long sAb, long sAh_,
    const __nv_bfloat16* __restrict__ Bh, const __nv_bfloat16* __restrict__ Bl,
    int ldb, long sBb, long sBh_,
    float* __restrict__ C0, __nv_bfloat16* __restrict__ Ch,
    __nv_bfloat16* __restrict__ Cl, int ldc, long sCb, long sCh_,
    int K, float alpha, int HB)
{
    const int z  = blockIdx.z;
    const int zb = z / HB, zh = z % HB;
    Ah += (size_t)zb * sAb + (size_t)zh * sAh_;
    Al += (size_t)zb * sAb + (size_t)zh * sAh_;
    Bh += (size_t)zb * sBb + (size_t)zh * sBh_;
    Bl += (size_t)zb * sBb + (size_t)zh * sBh_;
    const size_t coff = (size_t)zb * sCb + (size_t)zh * sCh_;

    __shared__ __nv_bfloat16 sA[2][2][128][PAD];
    __shared__ __nv_bfloat16 sB[2][2][128][PAD];

    const int tid  = threadIdx.x;
    const int lane = tid & 31;
    const int warp = tid >> 5;
    const int wm   = (warp >> 2) * 64;
    const int wn   = (warp & 3) * 32;
    const int bm   = blockIdx.y * 128;
    const int bn   = blockIdx.x * 128;

    const int lrow = tid >> 1;          // 0..127
    const int lch  = (tid & 1) * 8;     // elem offset 0/8

    float acc[4][4][4];
    #pragma unroll
    for (int i = 0; i < 4; i++)
        #pragma unroll
        for (int j = 0; j < 4; j++)
            #pragma unroll
            for (int c = 0; c < 4; c++) acc[i][j][c] = 0.f;

    const int lrow16 = lane & 15;
    const int ksub   = (lane >> 4) * 8;
    const int KT = K >> 4;

    // prologue
    {
        const size_t ar = (size_t)(bm + lrow) * lda + lch;
        const size_t br = (size_t)(bn + lrow) * ldb + lch;
        cpasync16(&sA[0][0][lrow][lch], Ah + ar);
        cpasync16(&sA[0][1][lrow][lch], Al + ar);
        cpasync16(&sB[0][0][lrow][lch], Bh + br);
        cpasync16(&sB[0][1][lrow][lch], Bl + br);
    }
    CP_COMMIT();

    for (int kt = 0; kt < KT; kt++) {
        const int st = kt & 1;
        if (kt + 1 < KT) {
            const int k0 = (kt + 1) << 4;
            const size_t ar = (size_t)(bm + lrow) * lda + k0 + lch;
            const size_t br = (size_t)(bn + lrow) * ldb + k0 + lch;
            cpasync16(&sA[st^1][0][lrow][lch], Ah + ar);
            cpasync16(&sA[st^1][1][lrow][lch], Al + ar);
            cpasync16(&sB[st^1][0][lrow][lch], Bh + br);
            cpasync16(&sB[st^1][1][lrow][lch], Bl + br);
        }
        CP_COMMIT();
        CP_WAIT1();
        __syncthreads();

        uint32_t ah[4][4], al[4][4], bh[4][2], bl[4][2];
        #pragma unroll
        for (int mi = 0; mi < 4; mi++) {
            ldsm_x4(ah[mi], smem_u32(&sA[st][0][wm + mi*16 + lrow16][ksub]));
            ldsm_x4(al[mi], smem_u32(&sA[st][1][wm + mi*16 + lrow16][ksub]));
        }
        #pragma unroll
        for (int np = 0; np < 2; np++) {
            uint32_t r[4];
            ldsm_x4(r, smem_u32(&sB[st][0][wn + np*16 + lrow16][ksub]));
            bh[2*np][0] = r[0]; bh[2*np+1][0] = r[1];
            bh[2*np][1] = r[2]; bh[2*np+1][1] = r[3];
            ldsm_x4(r, smem_u32(&sB[st][1][wn + np*16 + lrow16][ksub]));
            bl[2*np][0] = r[0]; bl[2*np+1][0] = r[1];
            bl[2*np][1] = r[2]; bl[2*np+1][1] = r[3];
        }

        #pragma unroll
        for (int mi = 0; mi < 4; mi++)
            #pragma unroll
            for (int ni = 0; ni < 4; ni++) {
                mma16816(acc[mi][ni], ah[mi], bh[ni][0], bh[ni][1]);
                mma16816(acc[mi][ni], ah[mi], bl[ni][0], bl[ni][1]);
                mma16816(acc[mi][ni], al[mi], bh[ni][0], bh[ni][1]);
            }
        __syncthreads();
    }

    const int g = lane >> 2, tg = lane & 3;
    #pragma unroll
    for (int mi = 0; mi < 4; mi++) {
        const int r0 = bm + wm + mi * 16 + g;
        #pragma unroll
        for (int ni = 0; ni < 4; ni++) {
            const int c0 = bn + wn + ni * 8 + tg * 2;
            float v00 = alpha * acc[mi][ni][0], v01 = alpha * acc[mi][ni][1];
            float v10 = alpha * acc[mi][ni][2], v11 = alpha * acc[mi][ni][3];
            if (MODE == 0) {
                *(float2*)&C0[coff + (size_t)r0 * ldc + c0]       = make_float2(v00, v01);
                *(float2*)&C0[coff + (size_t)(r0 + 8) * ldc + c0] = make_float2(v10, v11);
            } else {
                __nv_bfloat16 h0,h1,l0,l1;
                split1(v00,h0,l0); split1(v01,h1,l1);
                *(__nv_bfloat162*)&Ch[coff + (size_t)r0 * ldc + c0] = __halves2bfloat162(h0,h1);
                *(__nv_bfloat162*)&Cl[coff + (size_t)r0 * ldc + c0] = __halves2bfloat162(l0,l1);
                split1(v10,h0,l0); split1(v11,h1,l1);
                *(__nv_bfloat162*)&Ch[coff + (size_t)(r0+8) * ldc + c0] = __halves2bfloat162(h0,h1);
                *(__nv_bfloat162*)&Cl[coff + (size_t)(r0+8) * ldc + c0] = __halves2bfloat162(l0,l1);
            }
        }
    }
}

// ============================================================
// Fused softmax + head-mean. Reads fp32 scores, writes bf16 hi/lo probs
// + fp32 attn_weights.
// ============================================================
__global__ __launch_bounds__(256) void softmax_mean(
    const float* __restrict__ Sc, __nv_bfloat16* __restrict__ Ph,
    __nv_bfloat16* __restrict__ Pl, float* __restrict__ W)
{
    const int b = blockIdx.x >> 11;
    const int s = blockIdx.x & (S_ - 1);
    const int tid = threadIdx.x;
    const int lane = tid & 31, wid = tid >> 5;

    __shared__ float red[8];

    float acc[8];
    #pragma unroll
    for (int i = 0; i < 8; i++) acc[i] = 0.f;

    const int c0 = tid * 4;
    const int c1 = 1024 + tid * 4;

    for (int h = 0; h < H_; h++) {
        const size_t ro = ((size_t)(b * H_ + h) * S_ + s) * S_;
        float v[8];
        float4 f0 = *(const float4*)(Sc + ro + c0);
        float4 f1 = *(const float4*)(Sc + ro + c1);
        v[0]=f0.x; v[1]=f0.y; v[2]=f0.z; v[3]=f0.w;
        v[4]=f1.x; v[5]=f1.y; v[6]=f1.z; v[7]=f1.w;

        float m = v[0];
        #pragma unroll
        for (int i = 1; i < 8; i++) m = fmaxf(m, v[i]);
        #pragma unroll
        for (int o = 16; o > 0; o >>= 1) m = fmaxf(m, __shfl_xor_sync(0xffffffff, m, o));
        if (lane == 0) red[wid] = m;
        __syncthreads();
        if (wid == 0) {
            float t = red[lane & 7];
            #pragma unroll
            for (int o = 4; o > 0; o >>= 1) t = fmaxf(t, __shfl_xor_sync(0xffffffff, t, o));
            if (lane == 0) red[0] = t;
        }
        __syncthreads();
        m = red[0];
        __syncthreads();

        float sloc = 0.f;
        #pragma unroll
        for (int i = 0; i < 8; i++) { v[i] = __expf(v[i] - m); sloc += v[i]; }
        #pragma unroll
        for (int o = 16; o > 0; o >>= 1) sloc += __shfl_xor_sync(0xffffffff, sloc, o);
        if (lane == 0) red[wid] = sloc;
        __syncthreads();
        if (wid == 0) {
            float t = red[lane & 7];
            #pragma unroll
            for (int o = 4; o > 0; o >>= 1) t += __shfl_xor_sync(0xffffffff, t, o);
            if (lane == 0) red[0] = t;
        }
        __syncthreads();
        float inv = 1.0f / red[0];
        __syncthreads();

        __nv_bfloat16 ph[8], pl[8];
        #pragma unroll
        for (int i = 0; i < 8; i++) {
            v[i] *= inv;
            acc[i] += v[i] * (1.0f / H_);
            split1(v[i], ph[i], pl[i]);
        }
        *(__nv_bfloat162*)(Ph + ro + c0)     = __halves2bfloat162(ph[0], ph[1]);
        *(__nv_bfloat162*)(Ph + ro + c0 + 2) = __halves2bfloat162(ph[2], ph[3]);
        *(__nv_bfloat162*)(Ph + ro + c1)     = __halves2bfloat162(ph[4], ph[5]);
        *(__nv_bfloat162*)(Ph + ro + c1 + 2) = __halves2bfloat162(ph[6], ph[7]);
        *(__nv_bfloat162*)(Pl + ro + c0)     = __halves2bfloat162(pl[0], pl[1]);
        *(__nv_bfloat162*)(Pl + ro + c0 + 2) = __halves2bfloat162(pl[2], pl[3]);
        *(__nv_bfloat162*)(Pl + ro + c1)     = __halves2bfloat162(pl[4], pl[5]);
        *(__nv_bfloat162*)(Pl + ro + c1 + 2) = __halves2bfloat162(pl[6], pl[7]);
    }

    float* wrow = W + ((size_t)b * S_ + s) * S_;
    *(float4*)(wrow + c0) = make_float4(acc[0], acc[1], acc[2], acc[3]);
    *(float4*)(wrow + c1) = make_float4(acc[4], acc[5], acc[6], acc[7]);
}

// ============================================================
// attn @ V: O[s,d] = sum_k P[s,k]*V[k,d] per (b,h); bf16 hi/lo operands,
// cp.async 2-stage. Block 128x64, BK=16, 8 warps 4x2, warp 32x32.
// Writes split HO (hi/lo). __launch_bounds__(256,2) for 2 CTAs/SM.
// ============================================================
#define VPAD 72
__global__ __launch_bounds__(256, 2) void av_hl(
    const __nv_bfloat16* __restrict__ Ph, const __nv_bfloat16* __restrict__ Pl,
    const __nv_bfloat16* __restrict__ Vh, const __nv_bfloat16* __restrict__ Vl,
    __nv_bfloat16* __restrict__ Oh, __nv_bfloat16* __restrict__ Ol)
{
    const int z = blockIdx.z;
    const int b = z / H_, h = z % H_;
    const size_t po = (size_t)z * S_ * S_;
    const size_t vo = (size_t)b * S_ * D_ + h * DK_;

    __shared__ __nv_bfloat16 sP[2][2][128][PAD];
    __shared__ __nv_bfloat16 sV[2][2][16][VPAD];

    const int tid  = threadIdx.x;
    const int lane = tid & 31;
    const int warp = tid >> 5;
    const int wm   = (warp >> 1) * 32;
    const int wn   = (warp & 1) * 32;
    const int bm   = blockIdx.x * 128;

    const int lrow = tid >> 1;           // 0..127 (P rows)
    const int lch  = (tid & 1) * 8;
    const int vrow = tid >> 3;           // 0..31 (use <16)
    const int vch  = (tid & 7) * 8;

    float acc[2][4][4];
    #pragma unroll
    for (int i = 0; i < 2; i++)
        #pragma unroll
        for (int j = 0; j < 4; j++)
            #pragma unroll
            for (int c = 0; c < 4; c++) acc[i][j][c] = 0.f;

    const int lrow16 = lane & 15;
    const int ksub   = (lane >> 4) * 8;
    const int KT = S_ >> 4;   // 128

    {
        const size_t pr = po + (size_t)(bm + lrow) * S_ + lch;
        cpasync16(&sP[0][0][lrow][lch], Ph + pr);
        cpasync16(&sP[0][1][lrow][lch], Pl + pr);
        if (vrow < 16) {
            const size_t vr = vo + (size_t)vrow * D_ + vch;
            cpasync16(&sV[0][0][vrow][vch], Vh + vr);
            cpasync16(&sV[0][1][vrow][vch], Vl + vr);
        }
    }
    CP_COMMIT();

    for (int kt = 0; kt < KT; kt++) {
        const int st = kt & 1;
        if (kt + 1 < KT) {
            const int k0 = (kt + 1) << 4;
            const size_t pr = po + (size_t)(bm + lrow) * S_ + k0 + lch;
            cpasync16(&sP[st^1][0][lrow][lch], Ph + pr);
            cpasync16(&sP[st^1][1][lrow][lch], Pl + pr);
            if (vrow < 16) {
                const size_t vr = vo + (size_t)(k0 + vrow) * D_ + vch;
                cpasync16(&sV[st^1][0][vrow][vch], Vh + vr);
                cpasync16(&sV[st^1][1][vrow][vch], Vl + vr);
            }
        }
        CP_COMMIT();
        CP_WAIT1();
        __syncthreads();

        uint32_t ah[2][4], al[2][4], bh[4][2], bl[4][2];
        #pragma unroll
        for (int mi = 0; mi < 2; mi++) {
            ldsm_x4(ah[mi], smem_u32(&sP[st][0][wm + mi*16 + lrow16][ksub]));
            ldsm_x4(al[mi], smem_u32(&sP[st][1][wm + mi*16 + lrow16][ksub]));
        }
        #pragma unroll
        for (int np = 0; np < 2; np++) {
            uint32_t r[4];
            ldsm_x4_t(r, smem_u32(&sV[st][0][lrow16][wn + np*16 + ksub]));
            bh[2*np][0] = r[0]; bh[2*np][1] = r[1];
            bh[2*np+1][0] = r[2]; bh[2*np+1][1] = r[3];
            ldsm_x4_t(r, smem_u32(&sV[st][1][lrow16][wn + np*16 + ksub]));
            bl[2*np][0] = r[0]; bl[2*np][1] = r[1];
            bl[2*np+1][0] = r[2]; bl[2*np+1][1] = r[3];
        }

        #pragma unroll
        for (int mi = 0; mi < 2; mi++)
            #pragma unroll
            for (int ni = 0; ni < 4; ni++) {
                mma16816(acc[mi][ni], ah[mi], bh[ni][0], bh[ni][1]);
                mma16816(acc[mi][ni], ah[mi], bl[ni][0], bl[ni][1]);
                mma16816(acc[mi][ni], al[mi], bh[ni][0], bh[ni][1]);
            }
        __syncthreads();
    }

    const int g = lane >> 2, tg = lane & 3;
    #pragma unroll
    for (int mi = 0; mi < 2; mi++) {
        const int r0 = bm + wm + mi * 16 + g;
        #pragma unroll
        for (int ni = 0; ni < 4; ni++) {
            const int c0 = wn + ni * 8 + tg * 2;
            __nv_bfloat16 h0,h1,l0,l1;
            split1(acc[mi][ni][0], h0, l0); split1(acc[mi][ni][1], h1, l1);
            *(__nv_bfloat162*)&Oh[vo + (size_t)r0 * D_ + c0] = __halves2bfloat162(h0,h1);
            *(__nv_bfloat162*)&Ol[vo + (size_t)r0 * D_ + c0] = __halves2bfloat162(l0,l1);
            split1(acc[mi][ni][2], h0, l0); split1(acc[mi][ni][3], h1, l1);
            *(__nv_bfloat162*)&Oh[vo + (size_t)(r0+8) * D_ + c0] = __halves2bfloat162(h0,h1);
            *(__nv_bfloat162*)&Ol[vo + (size_t)(r0+8) * D_ + c0] = __halves2bfloat162(l0,l1);
        }
    }
}

// ============================================================
extern "C" void kernel_launch(void* const* d_in, const int* in_sizes, int n_in,
                              void* d_out, int out_size)
{
    const float* query = (const float*)d_in[0];
    const float* key   = (const float*)d_in[1];
    const float* value = (const float*)d_in[2];
    const float* W_q   = (const float*)d_in[3];
    const float* W_k   = (const float*)d_in[4];
    const float* W_v   = (const float*)d_in[5];
    const float* W_o   = (const float*)d_in[6];

    float* out   = (float*)d_out;
    float* attnw = out + (size_t)M_ * D_;

    float *Sc;
    __nv_bfloat16 *Ph, *Pl, *Qh, *Ql, *Kh, *Kl, *Vh, *Vl, *HOh, *HOl;
    __nv_bfloat16 *xqh, *xql, *xkh, *xkl, *xvh, *xvl;
    __nv_bfloat16 *wqh, *wql, *wkh, *wkl, *wvh, *wvl, *woh, *wol;
    cudaGetSymbolAddress((void**)&Sc,  g_S);
    cudaGetSymbolAddress((void**)&Ph,  g_Ph);
    cudaGetSymbolAddress((void**)&Pl,  g_Pl);
    cudaGetSymbolAddress((void**)&Qh,  g_Qh);  cudaGetSymbolAddress((void**)&Ql, g_Ql);
    cudaGetSymbolAddress((void**)&Kh,  g_Kh);  cudaGetSymbolAddress((void**)&Kl, g_Kl);
    cudaGetSymbolAddress((void**)&Vh,  g_Vh);  cudaGetSymbolAddress((void**)&Vl, g_Vl);
    cudaGetSymbolAddress((void**)&HOh, g_HOh); cudaGetSymbolAddress((void**)&HOl, g_HOl);
    cudaGetSymbolAddress((void**)&xqh, g_xqh); cudaGetSymbolAddress((void**)&xql, g_xql);
    cudaGetSymbolAddress((void**)&xkh, g_xkh); cudaGetSymbolAddress((void**)&xkl, g_xkl);
    cudaGetSymbolAddress((void**)&xvh, g_xvh); cudaGetSymbolAddress((void**)&xvl, g_xvl);
    cudaGetSymbolAddress((void**)&wqh, g_wqh); cudaGetSymbolAddress((void**)&wql, g_wql);
    cudaGetSymbolAddress((void**)&wkh, g_wkh); cudaGetSymbolAddress((void**)&wkl, g_wkl);
    cudaGetSymbolAddress((void**)&wvh, g_wvh); cudaGetSymbolAddress((void**)&wvl, g_wvl);
    cudaGetSymbolAddress((void**)&woh, g_woh); cudaGetSymbolAddress((void**)&wol, g_wol);

    dim3 blk(256);

    // 0) split-convert raw inputs (one launch)
    split_convert_all<<<2048, blk>>>(query, key, value, W_q, W_k, W_v, W_o,
                                     xqh, xql, xkh, xkl, xvh, xvl,
                                     wqh, wql, wkh, wkl, wvh, wvl, woh, wol);

    // 1) Projections (split outputs)
    {
        dim3 grid(D_/128, M_/128, 1);
        gemm_hl_nt<1><<<grid, blk>>>(xqh, xql, D_, 0, 0, wqh, wql, D_, 0, 0,
                                     nullptr, Qh, Ql, D_, 0, 0, D_, 1.0f, 1);
        gemm_hl_nt<1><<<grid, blk>>>(xkh, xkl, D_, 0, 0, wkh, wkl, D_, 0, 0,
                                     nullptr, Kh, Kl, D_, 0, 0, D_, 1.0f, 1);
        gemm_hl_nt<1><<<grid, blk>>>(xvh, xvl, D_, 0, 0, wvh, wvl, D_, 0, 0,
                                     nullptr, Vh, Vl, D_, 0, 0, D_, 1.0f, 1);
    }

    // 2) Scores (fp32 out)
    {
        dim3 grid(S_/128, S_/128, B_ * H_);
        gemm_hl_nt<0><<<grid, blk>>>(
            Qh, Ql, D_, (long)S_ * D_, DK_,
            Kh, Kl, D_, (long)S_ * D_, DK_,
            Sc, nullptr, nullptr, S_, (long)H_ * S_ * S_, (long)S_ * S_,
            DK_, 0.125f, H_);
    }

    // 3) Softmax + head mean (probs hi/lo out)
    softmax_mean<<<dim3(B_ * S_), blk>>>(Sc, Ph, Pl, attnw);

    // 4) head_out = attn @ V (split out)
    av_hl<<<dim3(S_/128, 1, B_ * H_), blk>>>(Ph, Pl, Vh, Vl, HOh, HOl);

    // 5) out = head_out @ W_o^T (fp32 out)
    {
        dim3 grid(D_/128, M_/128, 1);
        gemm_hl_nt<0><<<grid, blk>>>(HOh, HOl, D_, 0, 0, woh, wol, D_, 0, 0,
                                     out, nullptr, nullptr, D_, 0, 0, D_, 1.0f, 1);
    }
}

// round 8
// speedup vs baseline: 1.5807x; 1.0486x over previous
#include <cuda_runtime.h>
#include <cuda_bf16.h>
#include <math.h>
#include <stdint.h>

#define B_  2
#define S_  2048
#define D_  1024
#define H_  16
#define DK_ 64
#define M_  (B_*S_)   // 4096

// ---- scratch (static device globals; no allocation allowed) ----
__device__ float g_S[(size_t)B_*H_*S_*S_];                 // fp32 scores (512MB)
__device__ __nv_bfloat16 g_Ph[(size_t)B_*H_*S_*S_];        // probs hi (256MB)
__device__ __nv_bfloat16 g_Pl[(size_t)B_*H_*S_*S_];        // probs lo (256MB)
__device__ __nv_bfloat16 g_Qh[(size_t)M_*D_], g_Ql[(size_t)M_*D_];
__device__ __nv_bfloat16 g_Kh[(size_t)M_*D_], g_Kl[(size_t)M_*D_];
__device__ __nv_bfloat16 g_Vh[(size_t)M_*D_], g_Vl[(size_t)M_*D_];
__device__ __nv_bfloat16 g_HOh[(size_t)M_*D_], g_HOl[(size_t)M_*D_];
__device__ __nv_bfloat16 g_xqh[(size_t)M_*D_], g_xql[(size_t)M_*D_];
__device__ __nv_bfloat16 g_xkh[(size_t)M_*D_], g_xkl[(size_t)M_*D_];
__device__ __nv_bfloat16 g_xvh[(size_t)M_*D_], g_xvl[(size_t)M_*D_];
__device__ __nv_bfloat16 g_wqh[(size_t)D_*D_], g_wql[(size_t)D_*D_];
__device__ __nv_bfloat16 g_wkh[(size_t)D_*D_], g_wkl[(size_t)D_*D_];
__device__ __nv_bfloat16 g_wvh[(size_t)D_*D_], g_wvl[(size_t)D_*D_];
__device__ __nv_bfloat16 g_woh[(size_t)D_*D_], g_wol[(size_t)D_*D_];

// ============================================================
// helpers
// ============================================================
__device__ __forceinline__ uint32_t smem_u32(const void* p) {
    return (uint32_t)__cvta_generic_to_shared(p);
}
__device__ __forceinline__ void cpasync16(void* s, const void* g) {
    asm volatile("cp.async.cg.shared.global [%0], [%1], 16;\n"
                 :: "r"(smem_u32(s)), "l"(g));
}
#define CP_COMMIT() asm volatile("cp.async.commit_group;\n" ::)
#define CP_WAIT1()  asm volatile("cp.async.wait_group 1;\n" ::)

__device__ __forceinline__ void ldsm_x4(uint32_t* r, uint32_t a) {
    asm volatile("ldmatrix.sync.aligned.m8n8.x4.shared.b16 {%0,%1,%2,%3}, [%4];"
                 : "=r"(r[0]), "=r"(r[1]), "=r"(r[2]), "=r"(r[3]) : "r"(a));
}
__device__ __forceinline__ void ldsm_x4_t(uint32_t* r, uint32_t a) {
    asm volatile("ldmatrix.sync.aligned.m8n8.x4.trans.shared.b16 {%0,%1,%2,%3}, [%4];"
                 : "=r"(r[0]), "=r"(r[1]), "=r"(r[2]), "=r"(r[3]) : "r"(a));
}
__device__ __forceinline__ void mma16816(float* c, const uint32_t* a,
                                         uint32_t b0, uint32_t b1) {
    asm volatile(
        "mma.sync.aligned.m16n8k16.row.col.f32.bf16.bf16.f32 "
        "{%0,%1,%2,%3},{%4,%5,%6,%7},{%8,%9},{%0,%1,%2,%3};"
        : "+f"(c[0]), "+f"(c[1]), "+f"(c[2]), "+f"(c[3])
        : "r"(a[0]), "r"(a[1]), "r"(a[2]), "r"(a[3]), "r"(b0), "r"(b1));
}

// split fp32 -> bf16 hi + lo
__device__ __forceinline__ void split1(float v, __nv_bfloat16& h, __nv_bfloat16& l) {
    h = __float2bfloat16_rn(v);
    l = __float2bfloat16_rn(v - __bfloat162float(h));
}

// ============================================================
// one-shot grid-stride converter for all 7 input tensors
// ============================================================
#define NX4 ((M_*D_)/4)
#define NW4 ((D_*D_)/4)
__global__ __launch_bounds__(256) void split_convert_all(
    const float* __restrict__ xq, const float* __restrict__ xk,
    const float* __restrict__ xv, const float* __restrict__ wq,
    const float* __restrict__ wk, const float* __restrict__ wv,
    const float* __restrict__ wo,
    __nv_bfloat16* __restrict__ xqh, __nv_bfloat16* __restrict__ xql,
    __nv_bfloat16* __restrict__ xkh, __nv_bfloat16* __restrict__ xkl,
    __nv_bfloat16* __restrict__ xvh, __nv_bfloat16* __restrict__ xvl,
    __nv_bfloat16* __restrict__ wqh, __nv_bfloat16* __restrict__ wql,
    __nv_bfloat16* __restrict__ wkh, __nv_bfloat16* __restrict__ wkl,
    __nv_bfloat16* __restrict__ wvh, __nv_bfloat16* __restrict__ wvl,
    __nv_bfloat16* __restrict__ woh, __nv_bfloat16* __restrict__ wol)
{
    const int total = 3 * NX4 + 4 * NW4;
    for (int i = blockIdx.x * blockDim.x + threadIdx.x; i < total;
         i += gridDim.x * blockDim.x) {
        const float* src; __nv_bfloat16 *dh, *dl; int j = i;
        if (j < NX4)            { src = xq; dh = xqh; dl = xql; }
        else if ((j -= NX4) < NX4) { src = xk; dh = xkh; dl = xkl; }
        else if ((j -= NX4) < NX4) { src = xv; dh = xvh; dl = xvl; }
        else if ((j -= NX4) < NW4) { src = wq; dh = wqh; dl = wql; }
        else if ((j -= NW4) < NW4) { src = wk; dh = wkh; dl = wkl; }
        else if ((j -= NW4) < NW4) { src = wv; dh = wvh; dl = wvl; }
        else      { j -= NW4;    src = wo; dh = woh; dl = wol; }
        float4 v = *(const float4*)(src + (size_t)j * 4);
        __nv_bfloat16 h0,h1,h2,h3,l0,l1,l2,l3;
        split1(v.x,h0,l0); split1(v.y,h1,l1); split1(v.z,h2,l2); split1(v.w,h3,l3);
        *(__nv_bfloat162*)(dh + (size_t)j*4)     = __halves2bfloat162(h0,h1);
        *(__nv_bfloat162*)(dh + (size_t)j*4 + 2) = __halves2bfloat162(h2,h3);
        *(__nv_bfloat162*)(dl + (size_t)j*4)     = __halves2bfloat162(l0,l1);
        *(__nv_bfloat162*)(dl + (size_t)j*4 + 2) = __halves2bfloat162(l2,l3);
    }
}

// ============================================================
// Batched NT GEMM, bf16 hi/lo, 3-stage cp.async ring, 1 barrier/iter.
//   C[m,n] = alpha * sum_k (Ah+Al)[m,k]*(Bh+Bl)[n,k]   (3-term)
// Block 128x128, BK=16, 256 threads, 8 warps 2x4, warp 64x32.
// Dynamic smem: 3 stages x (Ah,Al,Bh,Bl)[128][PAD].
// MODE 0: fp32 C0.  MODE 1: split write Ch/Cl.
// ============================================================
#define PAD 24
#define MAT_E   (128 * PAD)           // elems per matrix buffer
#define STG_E   (4 * MAT_E)           // elems per stage
#define GEMM_SMEM (3 * STG_E * 2)     // bytes = 73728

template<int MODE>
__global__ __launch_bounds__(256, 2) void gemm_hl_nt(
    const __nv_bfloat16* __restrict__ Ah, const __nv_bfloat16* __restrict__ Al,
    int lda, long sAb, long sAh_,
    const __nv_bfloat16* __restrict__ Bh, const __nv_bfloat16* __restrict__ Bl,
    int ldb, long sBb, long sBh_,
    float* __restrict__ C0, __nv_bfloat16* __restrict__ Ch,
    __nv_bfloat16* __restrict__ Cl, int ldc, long sCb, long sCh_,
    int K, float alpha, int HB)
{
    extern __shared__ __nv_bfloat16 sm[];

    const int z  = blockIdx.z;
    const int zb = z / HB, zh = z % HB;
    Ah += (size_t)zb * sAb + (size_t)zh * sAh_;
    Al += (size_t)zb * sAb + (size_t)zh * sAh_;
    Bh += (size_t)zb * sBb + (size_t)zh * sBh_;
    Bl += (size_t)zb * sBb + (size_t)zh * sBh_;
    const size_t coff = (size_t)zb * sCb + (size_t)zh * sCh_;

    const int tid  = threadIdx.x;
    const int lane = tid & 31;
    const int warp = tid >> 5;
    const int wm   = (warp >> 2) * 64;
    const int wn   = (warp & 3) * 32;
    const int bm   = blockIdx.y * 128;
    const int bn   = blockIdx.x * 128;

    const int lrow = tid >> 1;          // 0..127
    const int lch  = (tid & 1) * 8;     // elem offset 0/8

    float acc[4][4][4];
    #pragma unroll
    for (int i = 0; i < 4; i++)
        #pragma unroll
        for (int j = 0; j < 4; j++)
            #pragma unroll
            for (int c = 0; c < 4; c++) acc[i][j][c] = 0.f;

    const int lrow16 = lane & 15;
    const int ksub   = (lane >> 4) * 8;
    const int KT = K >> 4;

    // smem write base for this thread (row lrow, col lch), per stage/matrix:
    const int wo_ = lrow * PAD + lch;

    // prologue: stages 0, 1
    #pragma unroll
    for (int s = 0; s < 2; s++) {
        if (s < KT) {
            const int k0 = s << 4;
            const size_t ar = (size_t)(bm + lrow) * lda + k0 + lch;
            const size_t br = (size_t)(bn + lrow) * ldb + k0 + lch;
            __nv_bfloat16* st = sm + s * STG_E;
            cpasync16(st + 0 * MAT_E + wo_, Ah + ar);
            cpasync16(st + 1 * MAT_E + wo_, Al + ar);
            cpasync16(st + 2 * MAT_E + wo_, Bh + br);
            cpasync16(st + 3 * MAT_E + wo_, Bl + br);
        }
        CP_COMMIT();
    }

    int st_idx = 0;
    for (int kt = 0; kt < KT; kt++) {
        CP_WAIT1();
        __syncthreads();

        // issue loads for stage kt+2 (after barrier -> no trailing barrier needed)
        {
            const int kn = kt + 2;
            if (kn < KT) {
                const int k0 = kn << 4;
                int sn = st_idx + 2; if (sn >= 3) sn -= 3;
                const size_t ar = (size_t)(bm + lrow) * lda + k0 + lch;
                const size_t br = (size_t)(bn + lrow) * ldb + k0 + lch;
                __nv_bfloat16* st = sm + sn * STG_E;
                cpasync16(st + 0 * MAT_E + wo_, Ah + ar);
                cpasync16(st + 1 * MAT_E + wo_, Al + ar);
                cpasync16(st + 2 * MAT_E + wo_, Bh + br);
                cpasync16(st + 3 * MAT_E + wo_, Bl + br);
            }
            CP_COMMIT();
        }

        __nv_bfloat16* stp = sm + st_idx * STG_E;
        const int aoff = (lrow16)*PAD + ksub;

        uint32_t ah[4][4], bh[4][2];
        // B-hi first (2 LDSM), then A-hi (4 LDSM) -> hi*hi MMAs can start early
        #pragma unroll
        for (int np = 0; np < 2; np++) {
            uint32_t r[4];
            ldsm_x4(r, smem_u32(stp + 2*MAT_E + (wn + np*16)*PAD + aoff));
            bh[2*np][0] = r[0]; bh[2*np+1][0] = r[1];
            bh[2*np][1] = r[2]; bh[2*np+1][1] = r[3];
        }
        #pragma unroll
        for (int mi = 0; mi < 4; mi++)
            ldsm_x4(ah[mi], smem_u32(stp + 0*MAT_E + (wm + mi*16)*PAD + aoff));
        #pragma unroll
        for (int mi = 0; mi < 4; mi++)
            #pragma unroll
            for (int ni = 0; ni < 4; ni++)
                mma16816(acc[mi][ni], ah[mi], bh[ni][0], bh[ni][1]);

        // B-lo -> ah * bl
        uint32_t bl[4][2];
        #pragma unroll
        for (int np = 0; np < 2; np++) {
            uint32_t r[4];
            ldsm_x4(r, smem_u32(stp + 3*MAT_E + (wn + np*16)*PAD + aoff));
            bl[2*np][0] = r[0]; bl[2*np+1][0] = r[1];
            bl[2*np][1] = r[2]; bl[2*np+1][1] = r[3];
        }
        #pragma unroll
        for (int mi = 0; mi < 4; mi++)
            #pragma unroll
            for (int ni = 0; ni < 4; ni++)
                mma16816(acc[mi][ni], ah[mi], bl[ni][0], bl[ni][1]);

        // A-lo -> al * bh  (reuse ah regs)
        #pragma unroll
        for (int mi = 0; mi < 4; mi++)
            ldsm_x4(ah[mi], smem_u32(stp + 1*MAT_E + (wm + mi*16)*PAD + aoff));
        #pragma unroll
        for (int mi = 0; mi < 4; mi++)
            #pragma unroll
            for (int ni = 0; ni < 4; ni++)
                mma16816(acc[mi][ni], ah[mi], bh[ni][0], bh[ni][1]);

        if (++st_idx == 3) st_idx = 0;
    }

    const int g = lane >> 2, tg = lane & 3;
    #pragma unroll
    for (int mi = 0; mi < 4; mi++) {
        const int r0 = bm + wm + mi * 16 + g;
        #pragma unroll
        for (int ni = 0; ni < 4; ni++) {
            const int c0 = bn + wn + ni * 8 + tg * 2;
            float v00 = alpha * acc[mi][ni][0], v01 = alpha * acc[mi][ni][1];
            float v10 = alpha * acc[mi][ni][2], v11 = alpha * acc[mi][ni][3];
            if (MODE == 0) {
                *(float2*)&C0[coff + (size_t)r0 * ldc + c0]       = make_float2(v00, v01);
                *(float2*)&C0[coff + (size_t)(r0 + 8) * ldc + c0] = make_float2(v10, v11);
            } else {
                __nv_bfloat16 h0,h1,l0,l1;
                split1(v00,h0,l0); split1(v01,h1,l1);
                *(__nv_bfloat162*)&Ch[coff + (size_t)r0 * ldc + c0] = __halves2bfloat162(h0,h1);
                *(__nv_bfloat162*)&Cl[coff + (size_t)r0 * ldc + c0] = __halves2bfloat162(l0,l1);
                split1(v10,h0,l0); split1(v11,h1,l1);
                *(__nv_bfloat162*)&Ch[coff + (size_t)(r0+8) * ldc + c0] = __halves2bfloat162(h0,h1);
                *(__nv_bfloat162*)&Cl[coff + (size_t)(r0+8) * ldc + c0] = __halves2bfloat162(l0,l1);
            }
        }
    }
}

// ============================================================
// Fused softmax + head-mean (unchanged).
// ============================================================
__global__ __launch_bounds__(256) void softmax_mean(
    const float* __restrict__ Sc, __nv_bfloat16* __restrict__ Ph,
    __nv_bfloat16* __restrict__ Pl, float* __restrict__ W)
{
    const int b = blockIdx.x >> 11;
    const int s = blockIdx.x & (S_ - 1);
    const int tid = threadIdx.x;
    const int lane = tid & 31, wid = tid >> 5;

    __shared__ float red[8];

    float acc[8];
    #pragma unroll
    for (int i = 0; i < 8; i++) acc[i] = 0.f;

    const int c0 = tid * 4;
    const int c1 = 1024 + tid * 4;

    for (int h = 0; h < H_; h++) {
        const size_t ro = ((size_t)(b * H_ + h) * S_ + s) * S_;
        float v[8];
        float4 f0 = *(const float4*)(Sc + ro + c0);
        float4 f1 = *(const float4*)(Sc + ro + c1);
        v[0]=f0.x; v[1]=f0.y; v[2]=f0.z; v[3]=f0.w;
        v[4]=f1.x; v[5]=f1.y; v[6]=f1.z; v[7]=f1.w;

        float m = v[0];
        #pragma unroll
        for (int i = 1; i < 8; i++) m = fmaxf(m, v[i]);
        #pragma unroll
        for (int o = 16; o > 0; o >>= 1) m = fmaxf(m, __shfl_xor_sync(0xffffffff, m, o));
        if (lane == 0) red[wid] = m;
        __syncthreads();
        if (wid == 0) {
            float t = red[lane & 7];
            #pragma unroll
            for (int o = 4; o > 0; o >>= 1) t = fmaxf(t, __shfl_xor_sync(0xffffffff, t, o));
            if (lane == 0) red[0] = t;
        }
        __syncthreads();
        m = red[0];
        __syncthreads();

        float sloc = 0.f;
        #pragma unroll
        for (int i = 0; i < 8; i++) { v[i] = __expf(v[i] - m); sloc += v[i]; }
        #pragma unroll
        for (int o = 16; o > 0; o >>= 1) sloc += __shfl_xor_sync(0xffffffff, sloc, o);
        if (lane == 0) red[wid] = sloc;
        __syncthreads();
        if (wid == 0) {
            float t = red[lane & 7];
            #pragma unroll
            for (int o = 4; o > 0; o >>= 1) t += __shfl_xor_sync(0xffffffff, t, o);
            if (lane == 0) red[0] = t;
        }
        __syncthreads();
        float inv = 1.0f / red[0];
        __syncthreads();

        __nv_bfloat16 ph[8], pl[8];
        #pragma unroll
        for (int i = 0; i < 8; i++) {
            v[i] *= inv;
            acc[i] += v[i] * (1.0f / H_);
            split1(v[i], ph[i], pl[i]);
        }
        *(__nv_bfloat162*)(Ph + ro + c0)     = __halves2bfloat162(ph[0], ph[1]);
        *(__nv_bfloat162*)(Ph + ro + c0 + 2) = __halves2bfloat162(ph[2], ph[3]);
        *(__nv_bfloat162*)(Ph + ro + c1)     = __halves2bfloat162(ph[4], ph[5]);
        *(__nv_bfloat162*)(Ph + ro + c1 + 2) = __halves2bfloat162(ph[6], ph[7]);
        *(__nv_bfloat162*)(Pl + ro + c0)     = __halves2bfloat162(pl[0], pl[1]);
        *(__nv_bfloat162*)(Pl + ro + c0 + 2) = __halves2bfloat162(pl[2], pl[3]);
        *(__nv_bfloat162*)(Pl + ro + c1)     = __halves2bfloat162(pl[4], pl[5]);
        *(__nv_bfloat162*)(Pl + ro + c1 + 2) = __halves2bfloat162(pl[6], pl[7]);
    }

    float* wrow = W + ((size_t)b * S_ + s) * S_;
    *(float4*)(wrow + c0) = make_float4(acc[0], acc[1], acc[2], acc[3]);
    *(float4*)(wrow + c1) = make_float4(acc[4], acc[5], acc[6], acc[7]);
}

// ============================================================
// attn @ V, 3-stage ring, 1 barrier/iter. Block 128x64, BK=16,
// 8 warps 4x2, warp 32x32. Writes split HO.
// ============================================================
#define VPAD 72
#define P_E   (128 * PAD)                 // per P matrix buffer
#define V_E   (16 * VPAD)                 // per V matrix buffer
#define AV_STG_E (2 * P_E + 2 * V_E)
#define AV_SMEM (3 * AV_STG_E * 2)        // bytes = 50688

__global__ __launch_bounds__(256, 2) void av_hl(
    const __nv_bfloat16* __restrict__ Ph, const __nv_bfloat16* __restrict__ Pl,
    const __nv_bfloat16* __restrict__ Vh, const __nv_bfloat16* __restrict__ Vl,
    __nv_bfloat16* __restrict__ Oh, __nv_bfloat16* __restrict__ Ol)
{
    extern __shared__ __nv_bfloat16 sm[];

    const int z = blockIdx.z;
    const int b = z / H_, h = z % H_;
    const size_t po = (size_t)z * S_ * S_;
    const size_t vo = (size_t)b * S_ * D_ + h * DK_;

    const int tid  = threadIdx.x;
    const int lane = tid & 31;
    const int warp = tid >> 5;
    const int wm   = (warp >> 1) * 32;
    const int wn   = (warp & 1) * 32;
    const int bm   = blockIdx.x * 128;

    const int lrow = tid >> 1;           // 0..127
    const int lch  = (tid & 1) * 8;
    const int vrow = tid >> 3;           // 0..31 (use <16)
    const int vch  = (tid & 7) * 8;

    float acc[2][4][4];
    #pragma unroll
    for (int i = 0; i < 2; i++)
        #pragma unroll
        for (int j = 0; j < 4; j++)
            #pragma unroll
            for (int c = 0; c < 4; c++) acc[i][j][c] = 0.f;

    const int lrow16 = lane & 15;
    const int ksub   = (lane >> 4) * 8;
    const int KT = S_ >> 4;   // 128

    const int pwo = lrow * PAD + lch;
    const int vwo = vrow * VPAD + vch;

    #pragma unroll
    for (int s = 0; s < 2; s++) {
        const int k0 = s << 4;
        __nv_bfloat16* st = sm + s * AV_STG_E;
        const size_t pr = po + (size_t)(bm + lrow) * S_ + k0 + lch;
        cpasync16(st + pwo,        Ph + pr);
        cpasync16(st + P_E + pwo,  Pl + pr);
        if (vrow < 16) {
            const size_t vr = vo + (size_t)(k0 + vrow) * D_ + vch;
            cpasync16(st + 2*P_E + vwo,       Vh + vr);
            cpasync16(st + 2*P_E + V_E + vwo, Vl + vr);
        }
        CP_COMMIT();
    }

    int st_idx = 0;
    for (int kt = 0; kt < KT; kt++) {
        CP_WAIT1();
        __syncthreads();

        {
            const int kn = kt + 2;
            if (kn < KT) {
                const int k0 = kn << 4;
                int sn = st_idx + 2; if (sn >= 3) sn -= 3;
                __nv_bfloat16* st = sm + sn * AV_STG_E;
                const size_t pr = po + (size_t)(bm + lrow) * S_ + k0 + lch;
                cpasync16(st + pwo,       Ph + pr);
                cpasync16(st + P_E + pwo, Pl + pr);
                if (vrow < 16) {
                    const size_t vr = vo + (size_t)(k0 + vrow) * D_ + vch;
                    cpasync16(st + 2*P_E + vwo,       Vh + vr);
                    cpasync16(st + 2*P_E + V_E + vwo, Vl + vr);
                }
            }
            CP_COMMIT();
        }

        __nv_bfloat16* stp = sm + st_idx * AV_STG_E;

        uint32_t ah[2][4], bh[4][2];
        #pragma unroll
        for (int np = 0; np < 2; np++) {
            uint32_t r[4];
            ldsm_x4_t(r, smem_u32(stp + 2*P_E + lrow16*VPAD + wn + np*16 + ksub));
            bh[2*np][0] = r[0]; bh[2*np][1] = r[1];
            bh[2*np+1][0] = r[2]; bh[2*np+1][1] = r[3];
        }
        #pragma unroll
        for (int mi = 0; mi < 2; mi++)
            ldsm_x4(ah[mi], smem_u32(stp + (wm + mi*16 + lrow16)*PAD + ksub));
        #pragma unroll
        for (int mi = 0; mi < 2; mi++)
            #pragma unroll
            for (int ni = 0; ni < 4; ni++)
                mma16816(acc[mi][ni], ah[mi], bh[ni][0], bh[ni][1]);

        uint32_t bl[4][2];
        #pragma unroll
        for (int np = 0; np < 2; np++) {
            uint32_t r[4];
            ldsm_x4_t(r, smem_u32(stp + 2*P_E + V_E + lrow16*VPAD + wn + np*16 + ksub));
            bl[2*np][0] = r[0]; bl[2*np][1] = r[1];
            bl[2*np+1][0] = r[2]; bl[2*np+1][1] = r[3];
        }
        #pragma unroll
        for (int mi = 0; mi < 2; mi++)
            #pragma unroll
            for (int ni = 0; ni < 4; ni++)
                mma16816(acc[mi][ni], ah[mi], bl[ni][0], bl[ni][1]);

        #pragma unroll
        for (int mi = 0; mi < 2; mi++)
            ldsm_x4(ah[mi], smem_u32(stp + P_E + (wm + mi*16 + lrow16)*PAD + ksub));
        #pragma unroll
        for (int mi = 0; mi < 2; mi++)
            #pragma unroll
            for (int ni = 0; ni < 4; ni++)
                mma16816(acc[mi][ni], ah[mi], bh[ni][0], bh[ni][1]);

        if (++st_idx == 3) st_idx = 0;
    }

    const int g = lane >> 2, tg = lane & 3;
    #pragma unroll
    for (int mi = 0; mi < 2; mi++) {
        const int r0 = bm + wm + mi * 16 + g;
        #pragma unroll
        for (int ni = 0; ni < 4; ni++) {
            const int c0 = wn + ni * 8 + tg * 2;
            __nv_bfloat16 h0,h1,l0,l1;
            split1(acc[mi][ni][0], h0, l0); split1(acc[mi][ni][1], h1, l1);
            *(__nv_bfloat162*)&Oh[vo + (size_t)r0 * D_ + c0] = __halves2bfloat162(h0,h1);
            *(__nv_bfloat162*)&Ol[vo + (size_t)r0 * D_ + c0] = __halves2bfloat162(l0,l1);
            split1(acc[mi][ni][2], h0, l0); split1(acc[mi][ni][3], h1, l1);
            *(__nv_bfloat162*)&Oh[vo + (size_t)(r0+8) * D_ + c0] = __halves2bfloat162(h0,h1);
            *(__nv_bfloat162*)&Ol[vo + (size_t)(r0+8) * D_ + c0] = __halves2bfloat162(l0,l1);
        }
    }
}

// ============================================================
extern "C" void kernel_launch(void* const* d_in, const int* in_sizes, int n_in,
                              void* d_out, int out_size)
{
    const float* query = (const float*)d_in[0];
    const float* key   = (const float*)d_in[1];
    const float* value = (const float*)d_in[2];
    const float* W_q   = (const float*)d_in[3];
    const float* W_k   = (const float*)d_in[4];
    const float* W_v   = (const float*)d_in[5];
    const float* W_o   = (const float*)d_in[6];

    float* out   = (float*)d_out;
    float* attnw = out + (size_t)M_ * D_;

    float *Sc;
    __nv_bfloat16 *Ph, *Pl, *Qh, *Ql, *Kh, *Kl, *Vh, *Vl, *HOh, *HOl;
    __nv_bfloat16 *xqh, *xql, *xkh, *xkl, *xvh, *xvl;
    __nv_bfloat16 *wqh, *wql, *wkh, *wkl, *wvh, *wvl, *woh, *wol;
    cudaGetSymbolAddress((void**)&Sc,  g_S);
    cudaGetSymbolAddress((void**)&Ph,  g_Ph);
    cudaGetSymbolAddress((void**)&Pl,  g_Pl);
    cudaGetSymbolAddress((void**)&Qh,  g_Qh);  cudaGetSymbolAddress((void**)&Ql, g_Ql);
    cudaGetSymbolAddress((void**)&Kh,  g_Kh);  cudaGetSymbolAddress((void**)&Kl, g_Kl);
    cudaGetSymbolAddress((void**)&Vh,  g_Vh);  cudaGetSymbolAddress((void**)&Vl, g_Vl);
    cudaGetSymbolAddress((void**)&HOh, g_HOh); cudaGetSymbolAddress((void**)&HOl, g_HOl);
    cudaGetSymbolAddress((void**)&xqh, g_xqh); cudaGetSymbolAddress((void**)&xql, g_xql);
    cudaGetSymbolAddress((void**)&xkh, g_xkh); cudaGetSymbolAddress((void**)&xkl, g_xkl);
    cudaGetSymbolAddress((void**)&xvh, g_xvh); cudaGetSymbolAddress((void**)&xvl, g_xvl);
    cudaGetSymbolAddress((void**)&wqh, g_wqh); cudaGetSymbolAddress((void**)&wql, g_wql);
    cudaGetSymbolAddress((void**)&wkh, g_wkh); cudaGetSymbolAddress((void**)&wkl, g_wkl);
    cudaGetSymbolAddress((void**)&wvh, g_wvh); cudaGetSymbolAddress((void**)&wvl, g_wvl);
    cudaGetSymbolAddress((void**)&woh, g_woh); cudaGetSymbolAddress((void**)&wol, g_wol);

    // raise dynamic smem limits (idempotent, cheap)
    cudaFuncSetAttribute(gemm_hl_nt<0>, cudaFuncAttributeMaxDynamicSharedMemorySize, GEMM_SMEM);
    cudaFuncSetAttribute(gemm_hl_nt<1>, cudaFuncAttributeMaxDynamicSharedMemorySize, GEMM_SMEM);
    cudaFuncSetAttribute(av_hl, cudaFuncAttributeMaxDynamicSharedMemorySize, AV_SMEM);

    dim3 blk(256);

    // 0) split-convert raw inputs (one launch)
    split_convert_all<<<2048, blk>>>(query, key, value, W_q, W_k, W_v, W_o,
                                     xqh, xql, xkh, xkl, xvh, xvl,
                                     wqh, wql, wkh, wkl, wvh, wvl, woh, wol);

    // 1) Projections (split outputs)
    {
        dim3 grid(D_/128, M_/128, 1);
        gemm_hl_nt<1><<<grid, blk, GEMM_SMEM>>>(xqh, xql, D_, 0, 0, wqh, wql, D_, 0, 0,
                                     nullptr, Qh, Ql, D_, 0, 0, D_, 1.0f, 1);
        gemm_hl_nt<1><<<grid, blk, GEMM_SMEM>>>(xkh, xkl, D_, 0, 0, wkh, wkl, D_, 0, 0,
                                     nullptr, Kh, Kl, D_, 0, 0, D_, 1.0f, 1);
        gemm_hl_nt<1><<<grid, blk, GEMM_SMEM>>>(xvh, xvl, D_, 0, 0, wvh, wvl, D_, 0, 0,
                                     nullptr, Vh, Vl, D_, 0, 0, D_, 1.0f, 1);
    }

    // 2) Scores (fp32 out)
    {
        dim3 grid(S_/128, S_/128, B_ * H_);
        gemm_hl_nt<0><<<grid, blk, GEMM_SMEM>>>(
            Qh, Ql, D_, (long)S_ * D_, DK_,
            Kh, Kl, D_, (long)S_ * D_, DK_,
            Sc, nullptr, nullptr, S_, (long)H_ * S_ * S_, (long)S_ * S_,
            DK_, 0.125f, H_);
    }

    // 3) Softmax + head mean (probs hi/lo out)
    softmax_mean<<<dim3(B_ * S_), blk>>>(Sc, Ph, Pl, attnw);

    // 4) head_out = attn @ V (split out)
    av_hl<<<dim3(S_/128, 1, B_ * H_), blk, AV_SMEM>>>(Ph, Pl, Vh, Vl, HOh, HOl);

    // 5) out = head_out @ W_o^T (fp32 out)
    {
        dim3 grid(D_/128, M_/128, 1);
        gemm_hl_nt<0><<<grid, blk, GEMM_SMEM>>>(HOh, HOl, D_, 0, 0, woh, wol, D_, 0, 0,
                                     out, nullptr, nullptr, D_, 0, 0, D_, 1.0f, 1);
    }
}